// round 2
// baseline (speedup 1.0000x reference)
#include <cuda_runtime.h>

#define BB 64
#define HH 512
#define LL 128
#define H4 2048

// persistent state (static device allocations are the sanctioned scratch path)
__device__ float g_ctx[(size_t)BB * LL * HH];  // [b][l][h]  16.8MB
__device__ float g_h[BB * HH];
__device__ float g_c[BB * HH];
__device__ float g_cat[BB * 2 * HH];           // [b][0:512]=hid, [512:1024]=h_t
__device__ float g_inp[BB * HH];
__device__ float g_mask[BB * LL];

// out layout (float32 concat of reference tuple)
#define OUT_PTR  (BB * LL * LL)
#define OUT_H    (OUT_PTR + BB * LL)
#define OUT_C    (OUT_H + BB * HH)

__device__ __forceinline__ float wsum(float v) {
#pragma unroll
    for (int off = 16; off; off >>= 1) v += __shfl_xor_sync(0xffffffffu, v, off);
    return v;
}

// ---------------- init: h, c, mask ----------------
__global__ void k_init(const float* __restrict__ h0, const float* __restrict__ c0) {
    int i = blockIdx.x * blockDim.x + threadIdx.x;
    if (i < BB * HH) { g_h[i] = h0[i]; g_c[i] = c0[i]; }
    if (i < BB * LL) g_mask[i] = 1.0f;
}

// ---------------- ctx precompute: ctx[b,l,h] = sum_d Wc[h,d]*context[b,d,l] + bc[h] ----------------
// grid (B, L/32), block 256. Each block: batch b, 32 l values, all 512 h.
__global__ __launch_bounds__(256) void k_ctx(const float* __restrict__ Wc,
                                             const float* __restrict__ bc,
                                             const float* __restrict__ ctxin) {
    __shared__ float s_in[256][36];  // [d_chunk][l], padded
    int b = blockIdx.x;
    int l0 = blockIdx.y * 32;
    int tid = threadIdx.x;
    int h0i = tid, h1i = tid + 256;

    float acc0[32], acc1[32];
    float bc0 = bc[h0i], bc1 = bc[h1i];
#pragma unroll
    for (int l = 0; l < 32; l++) { acc0[l] = bc0; acc1[l] = bc1; }

    for (int dc = 0; dc < HH; dc += 256) {
        __syncthreads();
        // thread loads context[b, dc+tid, l0 .. l0+32)
        const float* src = ctxin + ((size_t)b * HH + dc + tid) * LL + l0;
#pragma unroll
        for (int l = 0; l < 32; l += 4) {
            float4 v = *reinterpret_cast<const float4*>(src + l);
            *reinterpret_cast<float4*>(&s_in[tid][l]) = v;
        }
        __syncthreads();

        const float* w0 = Wc + (size_t)h0i * HH + dc;
        const float* w1 = Wc + (size_t)h1i * HH + dc;
        for (int d4 = 0; d4 < 256; d4 += 4) {
            float4 wa = *reinterpret_cast<const float4*>(w0 + d4);
            float4 wb = *reinterpret_cast<const float4*>(w1 + d4);
            float wav[4] = {wa.x, wa.y, wa.z, wa.w};
            float wbv[4] = {wb.x, wb.y, wb.z, wb.w};
#pragma unroll
            for (int dd = 0; dd < 4; dd++) {
                float a = wav[dd], bw = wbv[dd];
#pragma unroll
                for (int l = 0; l < 32; l += 4) {
                    float4 s = *reinterpret_cast<const float4*>(&s_in[d4 + dd][l]);
                    acc0[l + 0] += a * s.x; acc0[l + 1] += a * s.y;
                    acc0[l + 2] += a * s.z; acc0[l + 3] += a * s.w;
                    acc1[l + 0] += bw * s.x; acc1[l + 1] += bw * s.y;
                    acc1[l + 2] += bw * s.z; acc1[l + 3] += bw * s.w;
                }
            }
        }
    }
#pragma unroll
    for (int l = 0; l < 32; l++) {
        size_t base = ((size_t)b * LL + l0 + l) * HH;
        g_ctx[base + h0i] = acc0[l];
        g_ctx[base + h1i] = acc1[l];
    }
}

// ---------------- gates GEMM + LSTM cell ----------------
// grid (64 i-tiles, 4 b-tiles), block 256 (8 warps). Warp w: i = ibase+w, all 4 gates, 16 batches.
__global__ __launch_bounds__(256) void k_gates(const float* __restrict__ Whh,
                                               const float* __restrict__ bhh) {
    __shared__ float h_s[16][HH];
    int bbase = blockIdx.y * 16;
    int ibase = blockIdx.x * 8;
    int tid = threadIdx.x, lane = tid & 31, w = tid >> 5;

    for (int idx = tid; idx < 16 * HH; idx += 256) {
        int b = idx >> 9, k = idx & 511;
        h_s[b][k] = g_h[(bbase + b) * HH + k];
    }
    __syncthreads();

    int i = ibase + w;
    const float* wr0 = Whh + (size_t)(0 * HH + i) * HH;
    const float* wr1 = Whh + (size_t)(1 * HH + i) * HH;
    const float* wr2 = Whh + (size_t)(2 * HH + i) * HH;
    const float* wr3 = Whh + (size_t)(3 * HH + i) * HH;

    float acc[4][16];
#pragma unroll
    for (int g = 0; g < 4; g++)
#pragma unroll
        for (int b = 0; b < 16; b++) acc[g][b] = 0.f;

    for (int kk = 0; kk < 16; kk++) {
        int k = kk * 32 + lane;
        float w0 = wr0[k], w1 = wr1[k], w2 = wr2[k], w3 = wr3[k];
#pragma unroll
        for (int b = 0; b < 16; b++) {
            float hv = h_s[b][k];
            acc[0][b] += w0 * hv;
            acc[1][b] += w1 * hv;
            acc[2][b] += w2 * hv;
            acc[3][b] += w3 * hv;
        }
    }

    float gate[4] = {0.f, 0.f, 0.f, 0.f};
#pragma unroll
    for (int g = 0; g < 4; g++)
#pragma unroll
        for (int b = 0; b < 16; b++) {
            float v = wsum(acc[g][b]);
            if (lane == b) gate[g] = v;
        }

    if (lane < 16) {
        int b = bbase + lane;
        float ig = gate[0] + bhh[0 * HH + i];
        float fg = gate[1] + bhh[1 * HH + i];
        float gg = gate[2] + bhh[2 * HH + i];
        float og = gate[3] + bhh[3 * HH + i];
        float c_old = g_c[b * HH + i];
        float si = 1.f / (1.f + expf(-ig));
        float sf = 1.f / (1.f + expf(-fg));
        float so = 1.f / (1.f + expf(-og));
        float ct = sf * c_old + si * tanhf(gg);
        float ht = so * tanhf(ct);
        g_c[b * HH + i] = ct;
        g_cat[b * 2 * HH + HH + i] = ht;
    }
}

// ---------------- generic linear: out[b,r] = epi(sum_k W[r,k]*x[b,k] + bias[r]) ----------------
// grid (32 row-tiles, 4 b-tiles), block 256 (8 warps x 2 rows x 16 batches).
template <int KDIM, int EPI_TANH>
__global__ __launch_bounds__(256) void k_lin(const float* __restrict__ W,
                                             const float* __restrict__ bias,
                                             const float* __restrict__ xbase, int xstride,
                                             float* __restrict__ out, int ostride) {
    __shared__ float x_s[16][512];
    int bbase = blockIdx.y * 16;
    int rbase = blockIdx.x * 16;
    int tid = threadIdx.x, lane = tid & 31, wi = tid >> 5;
    int r0 = rbase + wi * 2;

    float acc[2][16];
#pragma unroll
    for (int r = 0; r < 2; r++)
#pragma unroll
        for (int b = 0; b < 16; b++) acc[r][b] = 0.f;

    for (int kc = 0; kc < KDIM; kc += 512) {
        __syncthreads();
        for (int idx = tid; idx < 16 * 512; idx += 256) {
            int b = idx >> 9, k = idx & 511;
            x_s[b][k] = xbase[(size_t)(bbase + b) * xstride + kc + k];
        }
        __syncthreads();
        const float* w0 = W + (size_t)r0 * KDIM + kc;
        const float* w1 = W + (size_t)(r0 + 1) * KDIM + kc;
        for (int kk = 0; kk < 16; kk++) {
            int k = kk * 32 + lane;
            float a0 = w0[k], a1 = w1[k];
#pragma unroll
            for (int b = 0; b < 16; b++) {
                float xv = x_s[b][k];
                acc[0][b] += a0 * xv;
                acc[1][b] += a1 * xv;
            }
        }
    }

    float res[2] = {0.f, 0.f};
#pragma unroll
    for (int r = 0; r < 2; r++)
#pragma unroll
        for (int b = 0; b < 16; b++) {
            float v = wsum(acc[r][b]);
            if (lane == b) res[r] = v;
        }

    if (lane < 16) {
        int b = bbase + lane;
#pragma unroll
        for (int r = 0; r < 2; r++) {
            float v = res[r] + bias[r0 + r];
            if (EPI_TANH) v = tanhf(v);
            out[(size_t)b * ostride + r0 + r] = v;
        }
    }
}

// ---------------- attention: scores + softmax + argmax + mask + hid ----------------
// grid 64 (one block per batch), block 512 (16 warps).
__global__ __launch_bounds__(512) void k_attn(const float* __restrict__ V,
                                              float* __restrict__ out, int t) {
    __shared__ float inp_s[HH];
    __shared__ float sc_s[LL];
    __shared__ float alpha_s[LL];
    __shared__ float mask_s[LL];
    int b = blockIdx.x;
    int tid = threadIdx.x, lane = tid & 31, w = tid >> 5;

    inp_s[tid] = g_inp[b * HH + tid];
    if (tid < LL) mask_s[tid] = g_mask[b * LL + tid];
    __syncthreads();

    float inpv[16], Vv[16];
#pragma unroll
    for (int m = 0; m < 16; m++) {
        inpv[m] = inp_s[m * 32 + lane];
        Vv[m] = V[m * 32 + lane];
    }

    // scores: warp w handles l = w*8 .. w*8+7
    for (int li = 0; li < 8; li++) {
        int l = w * 8 + li;
        const float* cp = g_ctx + ((size_t)b * LL + l) * HH + lane;
        float s = 0.f;
#pragma unroll
        for (int m = 0; m < 16; m++) {
            float cv = cp[m * 32];
            s += Vv[m] * tanhf(inpv[m] + cv);
        }
        s = wsum(s);
        if (lane == 0) sc_s[l] = s;
    }
    __syncthreads();

    if (w == 0) {
        float sv[4], mk[4];
#pragma unroll
        for (int j = 0; j < 4; j++) {
            mk[j] = mask_s[lane + 32 * j];
            sv[j] = (mk[j] != 0.f) ? sc_s[lane + 32 * j] : -3.4e38f;
        }
        float m = fmaxf(fmaxf(sv[0], sv[1]), fmaxf(sv[2], sv[3]));
#pragma unroll
        for (int off = 16; off; off >>= 1)
            m = fmaxf(m, __shfl_xor_sync(0xffffffffu, m, off));

        float e[4], sum = 0.f;
#pragma unroll
        for (int j = 0; j < 4; j++) {
            e[j] = (mk[j] != 0.f) ? expf(sv[j] - m) : 0.f;
            sum += e[j];
        }
        sum = wsum(sum);
        float inv = 1.f / sum;

        float best = -1.f;
        int bidx = 0;
#pragma unroll
        for (int j = 0; j < 4; j++) {
            int l = lane + 32 * j;
            float a = e[j] * inv;
            alpha_s[l] = a;
            out[(size_t)b * LL * LL + (size_t)t * LL + l] = a;
            float cand = (mk[j] != 0.f) ? a : -1.f;
            if (cand > best) { best = cand; bidx = l; }  // ascending l -> first index kept
        }
#pragma unroll
        for (int off = 16; off; off >>= 1) {
            float ob = __shfl_xor_sync(0xffffffffu, best, off);
            int oi = __shfl_xor_sync(0xffffffffu, bidx, off);
            if (ob > best || (ob == best && oi < bidx)) { best = ob; bidx = oi; }
        }
        if (lane == 0) {
            out[OUT_PTR + b * LL + t] = (float)bidx;
            g_mask[b * LL + bidx] = 0.f;
        }
    }
    __syncthreads();

    // hid[h] = sum_l ctx[b,l,h] * alpha[l]
    {
        float a = 0.f;
        const float* cp = g_ctx + (size_t)b * LL * HH + tid;
#pragma unroll 8
        for (int l = 0; l < LL; l++) a += cp[(size_t)l * HH] * alpha_s[l];
        g_cat[b * 2 * HH + tid] = a;
    }
}

// ---------------- final h/c copy ----------------
__global__ void k_fin(float* __restrict__ out) {
    int i = blockIdx.x * blockDim.x + threadIdx.x;
    if (i < BB * HH) {
        out[OUT_H + i] = g_h[i];
        out[OUT_C + i] = g_c[i];
    }
}

extern "C" void kernel_launch(void* const* d_in, const int* in_sizes, int n_in,
                              void* d_out, int out_size) {
    // metadata order: embedded_inputs, decoder_input, h0, c0, context,
    // W_hh, b_hh, W_in, b_in, W_ctx, b_ctx, V, W_out, b_out
    const float* h0   = (const float*)d_in[2];
    const float* c0   = (const float*)d_in[3];
    const float* ctxi = (const float*)d_in[4];
    const float* Whh  = (const float*)d_in[5];
    const float* bhh  = (const float*)d_in[6];
    const float* Win  = (const float*)d_in[7];
    const float* bin  = (const float*)d_in[8];
    const float* Wc   = (const float*)d_in[9];
    const float* bc   = (const float*)d_in[10];
    const float* V    = (const float*)d_in[11];
    const float* Wout = (const float*)d_in[12];
    const float* bout = (const float*)d_in[13];
    float* out = (float*)d_out;

    float *p_cat = nullptr, *p_inp = nullptr, *p_h = nullptr;
    cudaGetSymbolAddress((void**)&p_cat, g_cat);
    cudaGetSymbolAddress((void**)&p_inp, g_inp);
    cudaGetSymbolAddress((void**)&p_h, g_h);

    k_init<<<(BB * HH + 255) / 256, 256>>>(h0, c0);
    k_ctx<<<dim3(BB, LL / 32), 256>>>(Wc, bc, ctxi);

    for (int t = 0; t < LL; t++) {
        k_gates<<<dim3(64, 4), 256>>>(Whh, bhh);
        k_lin<512, 0><<<dim3(32, 4), 256>>>(Win, bin, p_cat + HH, 2 * HH, p_inp, HH);
        k_attn<<<BB, 512>>>(V, out, t);
        k_lin<1024, 1><<<dim3(32, 4), 256>>>(Wout, bout, p_cat, 2 * HH, p_h, HH);
    }
    k_fin<<<(BB * HH + 255) / 256, 256>>>(out);
}